// round 10
// baseline (speedup 1.0000x reference)
#include <cuda_runtime.h>
#include <cuda_bf16.h>
#include <cstdint>

#define BB 32
#define IN_C 512
#define HW 4096
#define CODE 256
#define NCLASSES 4
#define MEMN 20
#define DECAYF 0.9f
#define EPSF 1e-12f
#define NTP 128            // partials per (b,o): 32 n-tiles x 4 wn quarters

typedef long long ll;

// Deterministic scratch (no atomics anywhere).
__device__ float g_partial[BB * CODE * NTP];
__device__ float g_feat[BB * CODE];
__device__ float g_queue[NCLASSES * MEMN * CODE];

// Pre-converted bf16 hi/lo of Wp only (tiny).
__device__ __nv_bfloat16 g_wp_hi[CODE * IN_C];
__device__ __nv_bfloat16 g_wp_lo[CODE * IN_C];

// ---------------------------------------------------------------------------
// helpers
// ---------------------------------------------------------------------------
__device__ __forceinline__ uint32_t smem_u32(const void* p) {
    uint32_t a;
    asm("{ .reg .u64 t; cvta.to.shared.u64 t, %1; cvt.u32.u64 %0, t; }" : "=r"(a) : "l"(p));
    return a;
}
__device__ __forceinline__ void ldsm_x4(uint32_t a[4], uint32_t addr) {
    asm volatile("ldmatrix.sync.aligned.m8n8.x4.shared.b16 {%0,%1,%2,%3}, [%4];"
                 : "=r"(a[0]), "=r"(a[1]), "=r"(a[2]), "=r"(a[3]) : "r"(addr));
}
__device__ __forceinline__ void ldsm_x2t(uint32_t b[2], uint32_t addr) {
    asm volatile("ldmatrix.sync.aligned.m8n8.x2.trans.shared.b16 {%0,%1}, [%2];"
                 : "=r"(b[0]), "=r"(b[1]) : "r"(addr));
}
__device__ __forceinline__ void mma_bf16(float d[4], const uint32_t a[4], const uint32_t b[2]) {
    asm volatile("mma.sync.aligned.m16n8k16.row.col.f32.bf16.bf16.f32 "
                 "{%0,%1,%2,%3}, {%4,%5,%6,%7}, {%8,%9}, {%0,%1,%2,%3};"
                 : "+f"(d[0]), "+f"(d[1]), "+f"(d[2]), "+f"(d[3])
                 : "r"(a[0]), "r"(a[1]), "r"(a[2]), "r"(a[3]), "r"(b[0]), "r"(b[1]));
}
__device__ __forceinline__ void cpasync16(uint32_t dst, const void* src) {
    asm volatile("cp.async.cg.shared.global [%0], [%1], 16;" :: "r"(dst), "l"(src));
}
#define CP_COMMIT() asm volatile("cp.async.commit_group;" ::: "memory")
#define CP_WAIT0()  asm volatile("cp.async.wait_group 0;" ::: "memory")

// bf16 hi/lo split of a float4, packed 4xbf16 -> uint2
__device__ __forceinline__ void split4(float4 v, uint2& hi, uint2& lo) {
    __nv_bfloat16 h0 = __float2bfloat16_rn(v.x), h1 = __float2bfloat16_rn(v.y);
    __nv_bfloat16 h2 = __float2bfloat16_rn(v.z), h3 = __float2bfloat16_rn(v.w);
    float r0 = v.x - __bfloat162float(h0), r1 = v.y - __bfloat162float(h1);
    float r2 = v.z - __bfloat162float(h2), r3 = v.w - __bfloat162float(h3);
    __nv_bfloat16 l0 = __float2bfloat16_rn(r0), l1 = __float2bfloat16_rn(r1);
    __nv_bfloat16 l2 = __float2bfloat16_rn(r2), l3 = __float2bfloat16_rn(r3);
    hi.x = (uint32_t)__bfloat16_as_ushort(h0) | ((uint32_t)__bfloat16_as_ushort(h1) << 16);
    hi.y = (uint32_t)__bfloat16_as_ushort(h2) | ((uint32_t)__bfloat16_as_ushort(h3) << 16);
    lo.x = (uint32_t)__bfloat16_as_ushort(l0) | ((uint32_t)__bfloat16_as_ushort(l1) << 16);
    lo.y = (uint32_t)__bfloat16_as_ushort(l2) | ((uint32_t)__bfloat16_as_ushort(l3) << 16);
}
// split a single float to packed pair-of-pairs
__device__ __forceinline__ void split1(float v, __nv_bfloat16& h, __nv_bfloat16& l) {
    h = __float2bfloat16_rn(v);
    l = __float2bfloat16_rn(v - __bfloat162float(h));
}

// labels may be int32 or int64; detect on device (int64 -> odd words all zero).
__device__ __forceinline__ int get_label(const int* lab, int i) {
    bool odd_zero = true;
#pragma unroll
    for (int k = 1; k < 32; k += 2) odd_zero &= (lab[k] == 0);
    return odd_zero ? lab[2 * i] : lab[i];
}

// ===========================================================================
// Kernel 0: Wp fp32 -> bf16 hi/lo (131072 elems, trivial).
// ===========================================================================
__global__ __launch_bounds__(256) void convert_wp(const float* __restrict__ Wp) {
    const int i = (blockIdx.x * 256 + threadIdx.x) * 4;
    float4 v = *(const float4*)(Wp + i);
    uint2 hi, lo; split4(v, hi, lo);
    *(uint2*)(g_wp_hi + i) = hi;
    *(uint2*)(g_wp_lo + i) = lo;
}

// ===========================================================================
// Kernel 1: HMMA bf16-split GEMM, fused B conversion, M=256 CTA tile.
// (unchanged from round 9 — feats read once, 512 threads, 16 warps)
// ===========================================================================
#define KC 32
#define NCHUNK 16
#define A_STR 80
#define B_STR 272
#define A_HI 0
#define A_LO 20480
#define B_HI 40960
#define B_LO 49664
#define BUF 58368
#define PREDS (2 * BUF)
#define SMEM_GEMM (PREDS + 512 + 16)

__global__ __launch_bounds__(512, 1) void gemm_proj_mma(
    const float* __restrict__ feats, const float* __restrict__ preds,
    const float* __restrict__ bias_p, float* __restrict__ out)
{
    extern __shared__ char base[];
    const uint32_t sb = smem_u32(base);

    const int t = threadIdx.x, wid = t >> 5, lane = t & 31;
    const int nt = blockIdx.x, b = blockIdx.y;
    const int n0 = nt * 128;
    const int wm = wid & 3;
    const int wn = wid >> 2;

    const int ar = t >> 1, as0 = (t & 1) * 2;
    const __nv_bfloat16* wha = g_wp_hi + (ll)ar * IN_C + as0 * 8;
    const __nv_bfloat16* wla = g_wp_lo + (ll)ar * IN_C + as0 * 8;
    const uint32_t adst = sb + A_HI + ar * A_STR + as0 * 16;

    const int kr = t >> 4, nb = (t & 15) * 8;
    const float* fsrc = feats + ((ll)b * IN_C + kr) * HW + n0 + nb;
    const uint32_t bdst = sb + B_HI + kr * B_STR + nb * 2;

    if (t < 128) ((float*)(base + PREDS))[t] = preds[(ll)b * HW + n0 + t];

    float d[4][4][4];
#pragma unroll
    for (int i = 0; i < 4; i++)
#pragma unroll
        for (int j = 0; j < 4; j++)
#pragma unroll
            for (int k = 0; k < 4; k++) d[i][j][k] = 0.0f;

    float4 bR0, bR1;

    bR0 = *(const float4*)(fsrc);
    bR1 = *(const float4*)(fsrc + 4);
    cpasync16(adst,                      wha);
    cpasync16(adst + 16,                 wha + 8);
    cpasync16(adst + (A_LO - A_HI),      wla);
    cpasync16(adst + (A_LO - A_HI) + 16, wla + 8);
    CP_COMMIT();
    {
        uint2 h0, l0, h1, l1;
        split4(bR0, h0, l0); split4(bR1, h1, l1);
        *(uint4*)(base + (bdst - sb))                 = make_uint4(h0.x, h0.y, h1.x, h1.y);
        *(uint4*)(base + (bdst - sb) + (B_LO - B_HI)) = make_uint4(l0.x, l0.y, l1.x, l1.y);
    }
    CP_WAIT0();
    __syncthreads();

    for (int c = 0; c < NCHUNK; c++) {
        if (c + 1 < NCHUNK) {
            const ll ko = (ll)(c + 1) * KC;
            bR0 = *(const float4*)(fsrc + ko * HW);
            bR1 = *(const float4*)(fsrc + ko * HW + 4);
            const uint32_t db = ((c + 1) & 1) * BUF;
            cpasync16(adst + db,                      wha + ko);
            cpasync16(adst + db + 16,                 wha + ko + 8);
            cpasync16(adst + db + (A_LO - A_HI),      wla + ko);
            cpasync16(adst + db + (A_LO - A_HI) + 16, wla + ko + 8);
            CP_COMMIT();
        }

        const uint32_t bu = sb + (c & 1) * BUF;
#pragma unroll
        for (int s = 0; s < 2; s++) {
            uint32_t bh[4][2], bl[4][2];
            const int krr = s * 16 + (lane & 15);
#pragma unroll
            for (int nf = 0; nf < 4; nf++) {
                uint32_t ba = bu + B_HI + krr * B_STR + (wn * 32 + nf * 8) * 2;
                ldsm_x2t(bh[nf], ba);
                ldsm_x2t(bl[nf], ba + (B_LO - B_HI));
            }
#pragma unroll
            for (int mf = 0; mf < 4; mf++) {
                const int arr = wm * 64 + mf * 16 + (lane & 15);
                const uint32_t acol = (s * 16 + ((lane >> 4) << 3)) * 2;
                uint32_t aa = bu + A_HI + arr * A_STR + acol;
                uint32_t ah[4], al[4];
                ldsm_x4(ah, aa);
                ldsm_x4(al, aa + (A_LO - A_HI));
#pragma unroll
                for (int nf = 0; nf < 4; nf++) mma_bf16(d[mf][nf], ah, bh[nf]);
#pragma unroll
                for (int nf = 0; nf < 4; nf++) mma_bf16(d[mf][nf], ah, bl[nf]);
#pragma unroll
                for (int nf = 0; nf < 4; nf++) mma_bf16(d[mf][nf], al, bh[nf]);
            }
        }
        __syncthreads();

        if (c + 1 < NCHUNK) {
            const uint32_t db = ((c + 1) & 1) * BUF;
            uint2 h0, l0, h1, l1;
            split4(bR0, h0, l0); split4(bR1, h1, l1);
            *(uint4*)(base + (bdst - sb) + db)                 = make_uint4(h0.x, h0.y, h1.x, h1.y);
            *(uint4*)(base + (bdst - sb) + db + (B_LO - B_HI)) = make_uint4(l0.x, l0.y, l1.x, l1.y);
            CP_WAIT0();
        }
        __syncthreads();
    }

    const float* ps = (const float*)(base + PREDS);
    const int r = lane >> 2, cq = lane & 3;
#pragma unroll
    for (int mf = 0; mf < 4; mf++) {
        const int oa = wm * 64 + mf * 16 + r;
        const int oc = oa + 8;
        const float biasa = bias_p[oa], biasb = bias_p[oc];
        float* xa = out + ((ll)b * 2 * CODE + CODE + oa) * HW + n0;
        float* xc = out + ((ll)b * 2 * CODE + CODE + oc) * HW + n0;
        float ra = 0.0f, rb = 0.0f;
#pragma unroll
        for (int nf = 0; nf < 4; nf++) {
            const int nl = wn * 32 + nf * 8 + cq * 2;
            const float p0 = ps[nl], p1 = ps[nl + 1];
            float v0 = d[mf][nf][0] + biasa, v1 = d[mf][nf][1] + biasa;
            float v2 = d[mf][nf][2] + biasb, v3 = d[mf][nf][3] + biasb;
            ra += v0 * p0 + v1 * p1;
            rb += v2 * p0 + v3 * p1;
            *(float2*)(xa + nl) = make_float2(v0, v1);
            *(float2*)(xc + nl) = make_float2(v2, v3);
        }
        ra += __shfl_xor_sync(0xffffffffu, ra, 1);
        ra += __shfl_xor_sync(0xffffffffu, ra, 2);
        rb += __shfl_xor_sync(0xffffffffu, rb, 1);
        rb += __shfl_xor_sync(0xffffffffu, rb, 2);
        if (cq == 0) {
            g_partial[((ll)b * CODE + oa) * NTP + nt * 4 + wn] = ra;
            g_partial[((ll)b * CODE + oc) * NTP + nt * 4 + wn] = rb;
        }
    }
}

// ===========================================================================
// Kernel 2a: parallel feat reduction, coalesced.
// ===========================================================================
__global__ __launch_bounds__(1024) void feat_reduce_kernel() {
    const int gid = blockIdx.x * 1024 + threadIdx.x;
    const int row = gid >> 2, i = gid & 3;
    const float* p = g_partial + (ll)row * NTP + i * 4;
    float s = 0.0f;
#pragma unroll
    for (int q = 0; q < 8; q++) {
        float4 v = *(const float4*)(p + q * 16);
        s += v.x + v.y + v.z + v.w;
    }
    s += __shfl_xor_sync(0xffffffffu, s, 1);
    s += __shfl_xor_sync(0xffffffffu, s, 2);
    if (i == 0) g_feat[row] = s * (1.0f / HW);
}

// ===========================================================================
// Kernel 2b: class-parallel EMA scan. 4 blocks (one per class), each scans
// only its own samples in order -> ~4x shorter sequential chain.
// ===========================================================================
#define SMEM_SCAN ((MEMN * CODE + BB * CODE + 96) * 4)

__global__ __launch_bounds__(672) void queue_scan_kernel(
    const float* __restrict__ queue_in, const int* __restrict__ labels_raw,
    const int* __restrict__ flag)
{
    extern __shared__ float sm[];
    float* s_q = sm;                          // MEMN*CODE
    float* s_feat = sm + MEMN * CODE;         // BB*CODE
    float* s_logit = s_feat + BB * CODE;      // 20
    float* s_fnorm = s_logit + MEMN;          // 1
    float* s_coef  = s_fnorm + 1;             // 20
    int*   s_lab   = (int*)(s_coef + MEMN);   // 32

    const int cls = blockIdx.x;
    const int t = threadIdx.x;
    const float* qsrc = queue_in + (ll)cls * MEMN * CODE;
    for (int i = t; i < MEMN * CODE; i += 672) s_q[i] = qsrc[i];
    for (int i = t; i < BB * CODE; i += 672) s_feat[i] = g_feat[i];
    if (t < BB) s_lab[t] = get_label(labels_raw, t);
    __syncthreads();

    if (*flag == 1) {
        const int warp = t >> 5, lane = t & 31;
        for (int b = 0; b < BB; b++) {
            if (s_lab[b] != cls) continue;
            const float* f = s_feat + b * CODE;

            if (warp < MEMN) {
                const float* slot = s_q + warp * CODE;
                float s = 0.0f;
#pragma unroll
                for (int c = lane; c < CODE; c += 32) s += slot[c] * f[c];
#pragma unroll
                for (int off = 16; off; off >>= 1) s += __shfl_xor_sync(0xffffffffu, s, off);
                if (lane == 0) s_logit[warp] = s;
            } else {
                float s = 0.0f;
#pragma unroll
                for (int c = lane; c < CODE; c += 32) { float v = f[c]; s += v * v; }
#pragma unroll
                for (int off = 16; off; off >>= 1) s += __shfl_xor_sync(0xffffffffu, s, off);
                if (lane == 0) *s_fnorm = sqrtf(s);
            }
            __syncthreads();

            if (t < MEMN) {
                const float lg = s_logit[t];
                const float denom = fmaxf(fabsf(lg) * (*s_fnorm), EPSF);
                s_coef[t] = (1.0f - DECAYF) * lg / denom;
            }
            __syncthreads();

            for (int i = t; i < MEMN * CODE; i += 672) {
                const int m = i >> 8, c = i & 255;
                s_q[i] = DECAYF * s_q[i] + s_coef[m] * f[c];
            }
            __syncthreads();
        }
    }

    float* qdst = g_queue + (ll)cls * MEMN * CODE;
    for (int i = t; i < MEMN * CODE; i += 672) qdst[i] = s_q[i];
}

// ===========================================================================
// Kernel 3: tensor-core attention, 3-way bf16 split for BOTH GEMMs.
// Per CTA: one b, n-tile 64. 256 threads (8 warps). Grid (HW/64, BB) = 2048.
//  GEMM1: logits[32(m,pad)][64n] = q[32][256c] @ x[256c][64n], K chunked x8.
//  softmax over m in D-fragments (shfl-xor over m-groups, mask m>=20).
//  GEMM2: new_feat[256c][64n] = qT[256c][32m] @ attn[32m][64n].
// smem: Q[m][c] hi/lo (528-stride), QT[c][m] hi/lo (80), X dbl-buf (144),
//       ATTN (144).
// ===========================================================================
#define QS   528
#define QTS  80
#define XS   144
#define AS_  144
#define OFF_QHI   0
#define OFF_QLO   16896
#define OFF_QTHI  33792
#define OFF_QTLO  54272
#define OFF_X     74752      /* + buf*9216 ; lo = +4608 */
#define OFF_ATHI  93184
#define OFF_ATLO  97792
#define SMEM_ATTN 102400

__global__ __launch_bounds__(256, 2) void attn_mma_kernel(
    const int* __restrict__ labels_raw, float* __restrict__ out)
{
    extern __shared__ char base[];
    const uint32_t sb = smem_u32(base);

    const int t = threadIdx.x, wid = t >> 5, lane = t & 31;
    const int nt = blockIdx.x, b = blockIdx.y;
    const int n0 = nt * 64;
    const int g = lane >> 2;

    // ---- zero QT + ATTN regions (padded cols/rows must be clean) ----
    for (int i = OFF_QTHI + t * 16; i < OFF_QTHI + 2 * 20480; i += 256 * 16)
        *(uint4*)(base + i) = make_uint4(0, 0, 0, 0);
    for (int i = OFF_ATHI + t * 16; i < OFF_ATHI + 2 * 4608; i += 256 * 16)
        *(uint4*)(base + i) = make_uint4(0, 0, 0, 0);

    // ---- load q[l] (20x256 fp32), split into Q[m][c] and QT[c][m] ----
    const int l = get_label(labels_raw, b);
    const float* qsrc = g_queue + (ll)l * MEMN * CODE;
    __syncthreads();
    for (int i = t * 4; i < MEMN * CODE; i += 1024) {
        const int m = i >> 8, c = i & 255;
        float4 v = *(const float4*)(qsrc + i);
        uint2 hi, lo; split4(v, hi, lo);
        *(uint2*)(base + OFF_QHI + m * QS + c * 2) = hi;
        *(uint2*)(base + OFF_QLO + m * QS + c * 2) = lo;
        // transposed copies (scalar 2B stores)
        const float vv[4] = {v.x, v.y, v.z, v.w};
#pragma unroll
        for (int j = 0; j < 4; j++) {
            __nv_bfloat16 h, lw; split1(vv[j], h, lw);
            *(__nv_bfloat16*)(base + OFF_QTHI + (c + j) * QTS + m * 2) = h;
            *(__nv_bfloat16*)(base + OFF_QTLO + (c + j) * QTS + m * 2) = lw;
        }
    }

    // ---- GEMM1: logits, K=256 in 8 chunks of 32 ----
    const float* xb = out + ((ll)b * 2 * CODE + CODE) * HW;   // x half
    const int xkr = t >> 3;            // 0..31 (c row within chunk)
    const int xnq = (t & 7) * 8;       // 0..56
    const float* xsrc = xb + (ll)xkr * HW + n0 + xnq;

    float d1[2][4];
#pragma unroll
    for (int mf = 0; mf < 2; mf++)
#pragma unroll
        for (int k = 0; k < 4; k++) d1[mf][k] = 0.0f;

    float4 xr0, xr1;
    // prologue chunk 0
    xr0 = *(const float4*)(xsrc);
    xr1 = *(const float4*)(xsrc + 4);
    __syncthreads();   // Q/QT writes + zeroing visible
    {
        uint2 h0, l0, h1, l1;
        split4(xr0, h0, l0); split4(xr1, h1, l1);
        *(uint4*)(base + OFF_X + xkr * XS + xnq * 2)        = make_uint4(h0.x, h0.y, h1.x, h1.y);
        *(uint4*)(base + OFF_X + 4608 + xkr * XS + xnq * 2) = make_uint4(l0.x, l0.y, l1.x, l1.y);
    }
    __syncthreads();

    for (int kc = 0; kc < 8; kc++) {
        if (kc + 1 < 8) {
            const ll ko = (ll)(kc + 1) * 32;
            xr0 = *(const float4*)(xsrc + ko * HW);
            xr1 = *(const float4*)(xsrc + ko * HW + 4);
        }
        const uint32_t xu = sb + OFF_X + (kc & 1) * 9216;
#pragma unroll
        for (int s = 0; s < 2; s++) {
            uint32_t bh[2], bl[2];
            const uint32_t ba = xu + (s * 16 + (lane & 15)) * XS + wid * 16;
            ldsm_x2t(bh, ba);
            ldsm_x2t(bl, ba + 4608);
#pragma unroll
            for (int mf = 0; mf < 2; mf++) {
                const uint32_t aa = sb + OFF_QHI + (mf * 16 + (lane & 15)) * QS
                                  + (kc * 32 + s * 16 + ((lane >> 4) << 3)) * 2;
                uint32_t ah[4], al[4];
                ldsm_x4(ah, aa);
                ldsm_x4(al, aa + (OFF_QLO - OFF_QHI));
                mma_bf16(d1[mf], ah, bh);
                mma_bf16(d1[mf], ah, bl);
                mma_bf16(d1[mf], al, bh);
            }
        }
        __syncthreads();
        if (kc + 1 < 8) {
            const uint32_t db = ((kc + 1) & 1) * 9216;
            uint2 h0, l0, h1, l1;
            split4(xr0, h0, l0); split4(xr1, h1, l1);
            *(uint4*)(base + OFF_X + db + xkr * XS + xnq * 2)        = make_uint4(h0.x, h0.y, h1.x, h1.y);
            *(uint4*)(base + OFF_X + db + 4608 + xkr * XS + xnq * 2) = make_uint4(l0.x, l0.y, l1.x, l1.y);
            __syncthreads();
        }
    }

    // ---- softmax over m (rows: g, g+8, 16+g if g<4; mask the rest) ----
    float r0[2], r1[2], r2[2];
#pragma unroll
    for (int p = 0; p < 2; p++) {
        const float va = d1[0][p];
        const float vb = d1[0][2 + p];
        const float vc = (g < 4) ? d1[1][p] : -3.0e38f;
        float mx = fmaxf(fmaxf(va, vb), vc);
#pragma unroll
        for (int off = 4; off <= 16; off <<= 1)
            mx = fmaxf(mx, __shfl_xor_sync(0xffffffffu, mx, off));
        const float ea = __expf(va - mx);
        const float eb = __expf(vb - mx);
        const float ec = (g < 4) ? __expf(vc - mx) : 0.0f;
        float s = ea + eb + ec;
#pragma unroll
        for (int off = 4; off <= 16; off <<= 1)
            s += __shfl_xor_sync(0xffffffffu, s, off);
        const float inv = 1.0f / s;
        r0[p] = ea * inv; r1[p] = eb * inv; r2[p] = ec * inv;
    }
    // store attn (bf16 hi/lo) rows g, g+8, 16+g
    {
        const int coff = (wid * 8 + (lane & 3) * 2) * 2;
        __nv_bfloat16 h0, l0, h1, l1;
#pragma unroll
        for (int rsel = 0; rsel < 3; rsel++) {
            const float* rv = (rsel == 0) ? r0 : (rsel == 1) ? r1 : r2;
            const int row = (rsel == 0) ? g : (rsel == 1) ? 8 + g : 16 + g;
            if (rsel == 2 && g >= 4) break;
            split1(rv[0], h0, l0); split1(rv[1], h1, l1);
            *(uint32_t*)(base + OFF_ATHI + row * AS_ + coff) =
                (uint32_t)__bfloat16_as_ushort(h0) | ((uint32_t)__bfloat16_as_ushort(h1) << 16);
            *(uint32_t*)(base + OFF_ATLO + row * AS_ + coff) =
                (uint32_t)__bfloat16_as_ushort(l0) | ((uint32_t)__bfloat16_as_ushort(l1) << 16);
        }
    }
    __syncthreads();

    // ---- GEMM2: new_feat[c][n] = qT[c][m] @ attn[m][n], K=32 ----
    float d2[2][8][4];
#pragma unroll
    for (int mf = 0; mf < 2; mf++)
#pragma unroll
        for (int nf = 0; nf < 8; nf++)
#pragma unroll
            for (int k = 0; k < 4; k++) d2[mf][nf][k] = 0.0f;

#pragma unroll
    for (int s = 0; s < 2; s++) {
        uint32_t abh[8][2], abl[8][2];
        const uint32_t br = sb + OFF_ATHI + (s * 16 + (lane & 15)) * AS_;
#pragma unroll
        for (int nf = 0; nf < 8; nf++) {
            ldsm_x2t(abh[nf], br + nf * 16);
            ldsm_x2t(abl[nf], br + nf * 16 + (OFF_ATLO - OFF_ATHI));
        }
#pragma unroll
        for (int mf = 0; mf < 2; mf++) {
            const uint32_t qa = sb + OFF_QTHI + (wid * 32 + mf * 16 + (lane & 15)) * QTS
                              + (s * 16 + ((lane >> 4) << 3)) * 2;
            uint32_t qh[4], ql[4];
            ldsm_x4(qh, qa);
            ldsm_x4(ql, qa + (OFF_QTLO - OFF_QTHI));
#pragma unroll
            for (int nf = 0; nf < 8; nf++) mma_bf16(d2[mf][nf], qh, abh[nf]);
#pragma unroll
            for (int nf = 0; nf < 8; nf++) mma_bf16(d2[mf][nf], qh, abl[nf]);
#pragma unroll
            for (int nf = 0; nf < 8; nf++) mma_bf16(d2[mf][nf], ql, abh[nf]);
        }
    }

    // ---- write new_feat to out channels [0, 256) ----
    float* ob = out + ((ll)b * 2 * CODE) * HW + n0;
#pragma unroll
    for (int mf = 0; mf < 2; mf++) {
        const int c0 = wid * 32 + mf * 16 + g;
        const int nc = (lane & 3) * 2;
#pragma unroll
        for (int nf = 0; nf < 8; nf++) {
            *(float2*)(ob + (ll)c0 * HW + nf * 8 + nc)       = make_float2(d2[mf][nf][0], d2[mf][nf][1]);
            *(float2*)(ob + (ll)(c0 + 8) * HW + nf * 8 + nc) = make_float2(d2[mf][nf][2], d2[mf][nf][3]);
        }
    }
}

// ---------------------------------------------------------------------------
extern "C" void kernel_launch(void* const* d_in, const int* in_sizes, int n_in,
                              void* d_out, int out_size) {
    const float* feats  = (const float*)d_in[0];
    const float* preds  = (const float*)d_in[1];
    const int*   labels = (const int*)  d_in[2];
    const int*   flag   = (const int*)  d_in[3];
    const float* queue  = (const float*)d_in[4];
    const float* Wp     = (const float*)d_in[5];
    const float* bp     = (const float*)d_in[6];
    float* out = (float*)d_out;

    cudaFuncSetAttribute(gemm_proj_mma,
                         cudaFuncAttributeMaxDynamicSharedMemorySize, SMEM_GEMM);
    cudaFuncSetAttribute(queue_scan_kernel,
                         cudaFuncAttributeMaxDynamicSharedMemorySize, SMEM_SCAN);
    cudaFuncSetAttribute(attn_mma_kernel,
                         cudaFuncAttributeMaxDynamicSharedMemorySize, SMEM_ATTN);

    convert_wp<<<CODE * IN_C / 1024, 256>>>(Wp);

    dim3 g1(HW / 128, BB);
    gemm_proj_mma<<<g1, 512, SMEM_GEMM>>>(feats, preds, bp, out);

    feat_reduce_kernel<<<BB, 1024>>>();
    queue_scan_kernel<<<NCLASSES, 672, SMEM_SCAN>>>(queue, labels, flag);

    dim3 g3(HW / 64, BB);
    attn_mma_kernel<<<g3, 256, SMEM_ATTN>>>(labels, out);
}

// round 11
// speedup vs baseline: 1.5196x; 1.5196x over previous
#include <cuda_runtime.h>
#include <cuda_bf16.h>
#include <cstdint>

#define BB 32
#define IN_C 512
#define HW 4096
#define CODE 256
#define NCLASSES 4
#define MEMN 20
#define DECAYF 0.9f
#define EPSF 1e-12f
#define NTP 128

typedef long long ll;

// Deterministic scratch (no atomics anywhere).
__device__ float g_partial[BB * CODE * NTP];
__device__ float g_feat[BB * CODE];
__device__ float g_queue[NCLASSES * MEMN * CODE];

// Pre-converted bf16 hi/lo of Wp.
__device__ __nv_bfloat16 g_wp_hi[CODE * IN_C];
__device__ __nv_bfloat16 g_wp_lo[CODE * IN_C];

// Pre-split per-class q for attention (padded to 32 m; row-major and transposed).
__device__ __nv_bfloat16 g_qhi[NCLASSES * 32 * CODE];
__device__ __nv_bfloat16 g_qlo[NCLASSES * 32 * CODE];
__device__ __nv_bfloat16 g_qthi[NCLASSES * CODE * 32];
__device__ __nv_bfloat16 g_qtlo[NCLASSES * CODE * 32];

// ---------------------------------------------------------------------------
// helpers
// ---------------------------------------------------------------------------
__device__ __forceinline__ uint32_t smem_u32(const void* p) {
    uint32_t a;
    asm("{ .reg .u64 t; cvta.to.shared.u64 t, %1; cvt.u32.u64 %0, t; }" : "=r"(a) : "l"(p));
    return a;
}
__device__ __forceinline__ void ldsm_x4(uint32_t a[4], uint32_t addr) {
    asm volatile("ldmatrix.sync.aligned.m8n8.x4.shared.b16 {%0,%1,%2,%3}, [%4];"
                 : "=r"(a[0]), "=r"(a[1]), "=r"(a[2]), "=r"(a[3]) : "r"(addr));
}
__device__ __forceinline__ void ldsm_x2t(uint32_t b[2], uint32_t addr) {
    asm volatile("ldmatrix.sync.aligned.m8n8.x2.trans.shared.b16 {%0,%1}, [%2];"
                 : "=r"(b[0]), "=r"(b[1]) : "r"(addr));
}
__device__ __forceinline__ void mma_bf16(float d[4], const uint32_t a[4], const uint32_t b[2]) {
    asm volatile("mma.sync.aligned.m16n8k16.row.col.f32.bf16.bf16.f32 "
                 "{%0,%1,%2,%3}, {%4,%5,%6,%7}, {%8,%9}, {%0,%1,%2,%3};"
                 : "+f"(d[0]), "+f"(d[1]), "+f"(d[2]), "+f"(d[3])
                 : "r"(a[0]), "r"(a[1]), "r"(a[2]), "r"(a[3]), "r"(b[0]), "r"(b[1]));
}
__device__ __forceinline__ void cpasync16(uint32_t dst, const void* src) {
    asm volatile("cp.async.cg.shared.global [%0], [%1], 16;" :: "r"(dst), "l"(src));
}
#define CP_COMMIT() asm volatile("cp.async.commit_group;" ::: "memory")
#define CP_WAIT0()  asm volatile("cp.async.wait_group 0;" ::: "memory")

__device__ __forceinline__ void split4(float4 v, uint2& hi, uint2& lo) {
    __nv_bfloat16 h0 = __float2bfloat16_rn(v.x), h1 = __float2bfloat16_rn(v.y);
    __nv_bfloat16 h2 = __float2bfloat16_rn(v.z), h3 = __float2bfloat16_rn(v.w);
    float r0 = v.x - __bfloat162float(h0), r1 = v.y - __bfloat162float(h1);
    float r2 = v.z - __bfloat162float(h2), r3 = v.w - __bfloat162float(h3);
    __nv_bfloat16 l0 = __float2bfloat16_rn(r0), l1 = __float2bfloat16_rn(r1);
    __nv_bfloat16 l2 = __float2bfloat16_rn(r2), l3 = __float2bfloat16_rn(r3);
    hi.x = (uint32_t)__bfloat16_as_ushort(h0) | ((uint32_t)__bfloat16_as_ushort(h1) << 16);
    hi.y = (uint32_t)__bfloat16_as_ushort(h2) | ((uint32_t)__bfloat16_as_ushort(h3) << 16);
    lo.x = (uint32_t)__bfloat16_as_ushort(l0) | ((uint32_t)__bfloat16_as_ushort(l1) << 16);
    lo.y = (uint32_t)__bfloat16_as_ushort(l2) | ((uint32_t)__bfloat16_as_ushort(l3) << 16);
}
__device__ __forceinline__ void split1(float v, __nv_bfloat16& h, __nv_bfloat16& l) {
    h = __float2bfloat16_rn(v);
    l = __float2bfloat16_rn(v - __bfloat162float(h));
}

__device__ __forceinline__ int get_label(const int* lab, int i) {
    bool odd_zero = true;
#pragma unroll
    for (int k = 1; k < 32; k += 2) odd_zero &= (lab[k] == 0);
    return odd_zero ? lab[2 * i] : lab[i];
}

// ===========================================================================
// Kernel 0: Wp fp32 -> bf16 hi/lo.
// ===========================================================================
__global__ __launch_bounds__(256) void convert_wp(const float* __restrict__ Wp) {
    const int i = (blockIdx.x * 256 + threadIdx.x) * 4;
    float4 v = *(const float4*)(Wp + i);
    uint2 hi, lo; split4(v, hi, lo);
    *(uint2*)(g_wp_hi + i) = hi;
    *(uint2*)(g_wp_lo + i) = lo;
}

// ===========================================================================
// Kernel 1: HMMA bf16-split GEMM, fused B conversion, M=256 CTA tile.
// (unchanged from round 9)
// ===========================================================================
#define KC 32
#define NCHUNK 16
#define A_STR 80
#define B_STR 272
#define A_HI 0
#define A_LO 20480
#define B_HI 40960
#define B_LO 49664
#define BUF 58368
#define PREDS (2 * BUF)
#define SMEM_GEMM (PREDS + 512 + 16)

__global__ __launch_bounds__(512, 1) void gemm_proj_mma(
    const float* __restrict__ feats, const float* __restrict__ preds,
    const float* __restrict__ bias_p, float* __restrict__ out)
{
    extern __shared__ char base[];
    const uint32_t sb = smem_u32(base);

    const int t = threadIdx.x, wid = t >> 5, lane = t & 31;
    const int nt = blockIdx.x, b = blockIdx.y;
    const int n0 = nt * 128;
    const int wm = wid & 3;
    const int wn = wid >> 2;

    const int ar = t >> 1, as0 = (t & 1) * 2;
    const __nv_bfloat16* wha = g_wp_hi + (ll)ar * IN_C + as0 * 8;
    const __nv_bfloat16* wla = g_wp_lo + (ll)ar * IN_C + as0 * 8;
    const uint32_t adst = sb + A_HI + ar * A_STR + as0 * 16;

    const int kr = t >> 4, nb = (t & 15) * 8;
    const float* fsrc = feats + ((ll)b * IN_C + kr) * HW + n0 + nb;
    const uint32_t bdst = sb + B_HI + kr * B_STR + nb * 2;

    if (t < 128) ((float*)(base + PREDS))[t] = preds[(ll)b * HW + n0 + t];

    float d[4][4][4];
#pragma unroll
    for (int i = 0; i < 4; i++)
#pragma unroll
        for (int j = 0; j < 4; j++)
#pragma unroll
            for (int k = 0; k < 4; k++) d[i][j][k] = 0.0f;

    float4 bR0, bR1;

    bR0 = *(const float4*)(fsrc);
    bR1 = *(const float4*)(fsrc + 4);
    cpasync16(adst,                      wha);
    cpasync16(adst + 16,                 wha + 8);
    cpasync16(adst + (A_LO - A_HI),      wla);
    cpasync16(adst + (A_LO - A_HI) + 16, wla + 8);
    CP_COMMIT();
    {
        uint2 h0, l0, h1, l1;
        split4(bR0, h0, l0); split4(bR1, h1, l1);
        *(uint4*)(base + (bdst - sb))                 = make_uint4(h0.x, h0.y, h1.x, h1.y);
        *(uint4*)(base + (bdst - sb) + (B_LO - B_HI)) = make_uint4(l0.x, l0.y, l1.x, l1.y);
    }
    CP_WAIT0();
    __syncthreads();

    for (int c = 0; c < NCHUNK; c++) {
        if (c + 1 < NCHUNK) {
            const ll ko = (ll)(c + 1) * KC;
            bR0 = *(const float4*)(fsrc + ko * HW);
            bR1 = *(const float4*)(fsrc + ko * HW + 4);
            const uint32_t db = ((c + 1) & 1) * BUF;
            cpasync16(adst + db,                      wha + ko);
            cpasync16(adst + db + 16,                 wha + ko + 8);
            cpasync16(adst + db + (A_LO - A_HI),      wla + ko);
            cpasync16(adst + db + (A_LO - A_HI) + 16, wla + ko + 8);
            CP_COMMIT();
        }

        const uint32_t bu = sb + (c & 1) * BUF;
#pragma unroll
        for (int s = 0; s < 2; s++) {
            uint32_t bh[4][2], bl[4][2];
            const int krr = s * 16 + (lane & 15);
#pragma unroll
            for (int nf = 0; nf < 4; nf++) {
                uint32_t ba = bu + B_HI + krr * B_STR + (wn * 32 + nf * 8) * 2;
                ldsm_x2t(bh[nf], ba);
                ldsm_x2t(bl[nf], ba + (B_LO - B_HI));
            }
#pragma unroll
            for (int mf = 0; mf < 4; mf++) {
                const int arr = wm * 64 + mf * 16 + (lane & 15);
                const uint32_t acol = (s * 16 + ((lane >> 4) << 3)) * 2;
                uint32_t aa = bu + A_HI + arr * A_STR + acol;
                uint32_t ah[4], al[4];
                ldsm_x4(ah, aa);
                ldsm_x4(al, aa + (A_LO - A_HI));
#pragma unroll
                for (int nf = 0; nf < 4; nf++) mma_bf16(d[mf][nf], ah, bh[nf]);
#pragma unroll
                for (int nf = 0; nf < 4; nf++) mma_bf16(d[mf][nf], ah, bl[nf]);
#pragma unroll
                for (int nf = 0; nf < 4; nf++) mma_bf16(d[mf][nf], al, bh[nf]);
            }
        }
        __syncthreads();

        if (c + 1 < NCHUNK) {
            const uint32_t db = ((c + 1) & 1) * BUF;
            uint2 h0, l0, h1, l1;
            split4(bR0, h0, l0); split4(bR1, h1, l1);
            *(uint4*)(base + (bdst - sb) + db)                 = make_uint4(h0.x, h0.y, h1.x, h1.y);
            *(uint4*)(base + (bdst - sb) + db + (B_LO - B_HI)) = make_uint4(l0.x, l0.y, l1.x, l1.y);
            CP_WAIT0();
        }
        __syncthreads();
    }

    const float* ps = (const float*)(base + PREDS);
    const int r = lane >> 2, cq = lane & 3;
#pragma unroll
    for (int mf = 0; mf < 4; mf++) {
        const int oa = wm * 64 + mf * 16 + r;
        const int oc = oa + 8;
        const float biasa = bias_p[oa], biasb = bias_p[oc];
        float* xa = out + ((ll)b * 2 * CODE + CODE + oa) * HW + n0;
        float* xc = out + ((ll)b * 2 * CODE + CODE + oc) * HW + n0;
        float ra = 0.0f, rb = 0.0f;
#pragma unroll
        for (int nf = 0; nf < 4; nf++) {
            const int nl = wn * 32 + nf * 8 + cq * 2;
            const float p0 = ps[nl], p1 = ps[nl + 1];
            float v0 = d[mf][nf][0] + biasa, v1 = d[mf][nf][1] + biasa;
            float v2 = d[mf][nf][2] + biasb, v3 = d[mf][nf][3] + biasb;
            ra += v0 * p0 + v1 * p1;
            rb += v2 * p0 + v3 * p1;
            *(float2*)(xa + nl) = make_float2(v0, v1);
            *(float2*)(xc + nl) = make_float2(v2, v3);
        }
        ra += __shfl_xor_sync(0xffffffffu, ra, 1);
        ra += __shfl_xor_sync(0xffffffffu, ra, 2);
        rb += __shfl_xor_sync(0xffffffffu, rb, 1);
        rb += __shfl_xor_sync(0xffffffffu, rb, 2);
        if (cq == 0) {
            g_partial[((ll)b * CODE + oa) * NTP + nt * 4 + wn] = ra;
            g_partial[((ll)b * CODE + oc) * NTP + nt * 4 + wn] = rb;
        }
    }
}

// ===========================================================================
// Kernel 2a: parallel feat reduction, coalesced.
// ===========================================================================
__global__ __launch_bounds__(1024) void feat_reduce_kernel() {
    const int gid = blockIdx.x * 1024 + threadIdx.x;
    const int row = gid >> 2, i = gid & 3;
    const float* p = g_partial + (ll)row * NTP + i * 4;
    float s = 0.0f;
#pragma unroll
    for (int q = 0; q < 8; q++) {
        float4 v = *(const float4*)(p + q * 16);
        s += v.x + v.y + v.z + v.w;
    }
    s += __shfl_xor_sync(0xffffffffu, s, 1);
    s += __shfl_xor_sync(0xffffffffu, s, 2);
    if (i == 0) g_feat[row] = s * (1.0f / HW);
}

// ===========================================================================
// Kernel 2b: class-parallel EMA scan (4 blocks).
// ===========================================================================
#define SMEM_SCAN ((MEMN * CODE + BB * CODE + 96) * 4)

__global__ __launch_bounds__(672) void queue_scan_kernel(
    const float* __restrict__ queue_in, const int* __restrict__ labels_raw,
    const int* __restrict__ flag)
{
    extern __shared__ float sm[];
    float* s_q = sm;
    float* s_feat = sm + MEMN * CODE;
    float* s_logit = s_feat + BB * CODE;
    float* s_fnorm = s_logit + MEMN;
    float* s_coef  = s_fnorm + 1;
    int*   s_lab   = (int*)(s_coef + MEMN);

    const int cls = blockIdx.x;
    const int t = threadIdx.x;
    const float* qsrc = queue_in + (ll)cls * MEMN * CODE;
    for (int i = t; i < MEMN * CODE; i += 672) s_q[i] = qsrc[i];
    for (int i = t; i < BB * CODE; i += 672) s_feat[i] = g_feat[i];
    if (t < BB) s_lab[t] = get_label(labels_raw, t);
    __syncthreads();

    if (*flag == 1) {
        const int warp = t >> 5, lane = t & 31;
        for (int b = 0; b < BB; b++) {
            if (s_lab[b] != cls) continue;
            const float* f = s_feat + b * CODE;

            if (warp < MEMN) {
                const float* slot = s_q + warp * CODE;
                float s = 0.0f;
#pragma unroll
                for (int c = lane; c < CODE; c += 32) s += slot[c] * f[c];
#pragma unroll
                for (int off = 16; off; off >>= 1) s += __shfl_xor_sync(0xffffffffu, s, off);
                if (lane == 0) s_logit[warp] = s;
            } else {
                float s = 0.0f;
#pragma unroll
                for (int c = lane; c < CODE; c += 32) { float v = f[c]; s += v * v; }
#pragma unroll
                for (int off = 16; off; off >>= 1) s += __shfl_xor_sync(0xffffffffu, s, off);
                if (lane == 0) *s_fnorm = sqrtf(s);
            }
            __syncthreads();

            if (t < MEMN) {
                const float lg = s_logit[t];
                const float denom = fmaxf(fabsf(lg) * (*s_fnorm), EPSF);
                s_coef[t] = (1.0f - DECAYF) * lg / denom;
            }
            __syncthreads();

            for (int i = t; i < MEMN * CODE; i += 672) {
                const int m = i >> 8, c = i & 255;
                s_q[i] = DECAYF * s_q[i] + s_coef[m] * f[c];
            }
            __syncthreads();
        }
    }

    float* qdst = g_queue + (ll)cls * MEMN * CODE;
    for (int i = t; i < MEMN * CODE; i += 672) qdst[i] = s_q[i];
}

// ===========================================================================
// Kernel 2c: per-class q pre-split for attention (row-major padded + transposed).
// Grid NCLASSES, 256 threads. Tiny.
// ===========================================================================
__global__ __launch_bounds__(256) void prep_attn_q() {
    const int cls = blockIdx.x, t = threadIdx.x;
    const float* q = g_queue + (ll)cls * MEMN * CODE;
    const int gb = cls * 32 * CODE;

    for (int i = t * 4; i < 32 * CODE; i += 1024) {
        const int m = i >> 8;
        float4 v = (m < MEMN) ? *(const float4*)(q + (i & (32 * CODE - 1)) - (m << 8) + m * CODE + (i & 255))
                              : make_float4(0.f, 0.f, 0.f, 0.f);
        // simpler: recompute directly
        v = (m < MEMN) ? *(const float4*)(q + m * CODE + (i & 255)) : make_float4(0.f, 0.f, 0.f, 0.f);
        uint2 hi, lo; split4(v, hi, lo);
        *(uint2*)(g_qhi + gb + i) = hi;
        *(uint2*)(g_qlo + gb + i) = lo;
    }
    for (int idx = t; idx < CODE * 32; idx += 256) {
        const int c = idx >> 5, m = idx & 31;
        const float v = (m < MEMN) ? q[m * CODE + c] : 0.0f;
        __nv_bfloat16 h, l; split1(v, h, l);
        g_qthi[gb + idx] = h;
        g_qtlo[gb + idx] = l;
    }
}

// ===========================================================================
// Kernel 3: tensor-core attention, n-tile 128, pre-split q via cp.async.
//  GEMM1: logits[32m][128n] = Q[32][256] @ x[256][128], K chunked x8.
//  fragment softmax over m (validated in round 10).
//  GEMM2: new_feat[256c][128n] = QT[256][32] @ attn[32][128], two n-halves.
// ===========================================================================
#define QS   528
#define QTS  80
#define XS2  272
#define ATS  272
#define OFF_QHI   0
#define OFF_QLO   16896
#define OFF_QTHI  33792
#define OFF_QTLO  54272
#define OFF_X     74752      /* per-buf 17408 (hi 8704 + lo 8704), 2 bufs */
#define OFF_ATHI  109568
#define OFF_ATLO  118272
#define SMEM_ATTN 126976

__global__ __launch_bounds__(256, 1) void attn_mma_kernel(
    const int* __restrict__ labels_raw, float* __restrict__ out)
{
    extern __shared__ char base[];
    const uint32_t sb = smem_u32(base);

    const int t = threadIdx.x, wid = t >> 5, lane = t & 31;
    const int nt = blockIdx.x, b = blockIdx.y;
    const int n0 = nt * 128;
    const int g = lane >> 2;

    const int l = get_label(labels_raw, b);
    const int gb = l * 32 * CODE;

    // ---- cp.async pre-split q into smem (16 chunks / thread) ----
    {
        const int ch = t * 4;
#pragma unroll
        for (int q4 = 0; q4 < 4; q4++) {
            const int cc = ch + q4;
            const int row = cc >> 5, seg = cc & 31;            // Q: 32 rows x 32 segs
            cpasync16(sb + OFF_QHI + row * QS + seg * 16, g_qhi + gb + row * CODE + seg * 8);
            cpasync16(sb + OFF_QLO + row * QS + seg * 16, g_qlo + gb + row * CODE + seg * 8);
            const int c = cc >> 2, s2 = cc & 3;                // QT: 256 rows x 4 segs
            cpasync16(sb + OFF_QTHI + c * QTS + s2 * 16, g_qthi + gb + c * 32 + s2 * 8);
            cpasync16(sb + OFF_QTLO + c * QTS + s2 * 16, g_qtlo + gb + c * 32 + s2 * 8);
        }
        CP_COMMIT();
    }

    // ---- zero ATTN region (padded rows must stay zero) ----
    for (int i = t * 16; i < 17408; i += 4096)
        *(uint4*)(base + OFF_ATHI + i) = make_uint4(0, 0, 0, 0);

    // ---- X staging mapping: 32 c-rows x 128 n per chunk, 16 floats/thread ----
    const int xkr = t >> 3, xnq = (t & 7) * 16;
    const float* xsrc = out + ((ll)b * 2 * CODE + CODE + xkr) * HW + n0 + xnq;
    const uint32_t xdoff = xkr * XS2 + xnq * 2;   // byte offset within region

    float4 xr[4];
#pragma unroll
    for (int q = 0; q < 4; q++) xr[q] = *(const float4*)(xsrc + q * 4);
    {
        uint2 h0, l0, h1, l1, h2, l2, h3, l3;
        split4(xr[0], h0, l0); split4(xr[1], h1, l1);
        split4(xr[2], h2, l2); split4(xr[3], h3, l3);
        *(uint4*)(base + OFF_X + xdoff)          = make_uint4(h0.x, h0.y, h1.x, h1.y);
        *(uint4*)(base + OFF_X + xdoff + 16)     = make_uint4(h2.x, h2.y, h3.x, h3.y);
        *(uint4*)(base + OFF_X + 8704 + xdoff)      = make_uint4(l0.x, l0.y, l1.x, l1.y);
        *(uint4*)(base + OFF_X + 8704 + xdoff + 16) = make_uint4(l2.x, l2.y, l3.x, l3.y);
    }
    CP_WAIT0();
    __syncthreads();

    // ---- GEMM1: logits ----
    float d1[2][2][4];
#pragma unroll
    for (int mf = 0; mf < 2; mf++)
#pragma unroll
        for (int nf = 0; nf < 2; nf++)
#pragma unroll
            for (int k = 0; k < 4; k++) d1[mf][nf][k] = 0.0f;

    for (int kc = 0; kc < 8; kc++) {
        if (kc + 1 < 8) {
            const ll ko = (ll)(kc + 1) * 32;
#pragma unroll
            for (int q = 0; q < 4; q++) xr[q] = *(const float4*)(xsrc + ko * HW + q * 4);
        }
        const uint32_t xu = sb + OFF_X + (kc & 1) * 17408;
#pragma unroll
        for (int s = 0; s < 2; s++) {
            uint32_t bh[2][2], bl[2][2];
            const uint32_t brow = xu + (s * 16 + (lane & 15)) * XS2;
#pragma unroll
            for (int nf = 0; nf < 2; nf++) {
                ldsm_x2t(bh[nf], brow + (wid * 16 + nf * 8) * 2);
                ldsm_x2t(bl[nf], brow + (wid * 16 + nf * 8) * 2 + 8704);
            }
#pragma unroll
            for (int mf = 0; mf < 2; mf++) {
                const uint32_t aa = sb + OFF_QHI + (mf * 16 + (lane & 15)) * QS
                                  + (kc * 32 + s * 16 + ((lane >> 4) << 3)) * 2;
                uint32_t ah[4], al[4];
                ldsm_x4(ah, aa);
                ldsm_x4(al, aa + (OFF_QLO - OFF_QHI));
#pragma unroll
                for (int nf = 0; nf < 2; nf++) {
                    mma_bf16(d1[mf][nf], ah, bh[nf]);
                    mma_bf16(d1[mf][nf], ah, bl[nf]);
                    mma_bf16(d1[mf][nf], al, bh[nf]);
                }
            }
        }
        __syncthreads();
        if (kc + 1 < 8) {
            const uint32_t db = ((kc + 1) & 1) * 17408;
            uint2 h0, l0, h1, l1, h2, l2, h3, l3;
            split4(xr[0], h0, l0); split4(xr[1], h1, l1);
            split4(xr[2], h2, l2); split4(xr[3], h3, l3);
            *(uint4*)(base + OFF_X + db + xdoff)          = make_uint4(h0.x, h0.y, h1.x, h1.y);
            *(uint4*)(base + OFF_X + db + xdoff + 16)     = make_uint4(h2.x, h2.y, h3.x, h3.y);
            *(uint4*)(base + OFF_X + db + 8704 + xdoff)      = make_uint4(l0.x, l0.y, l1.x, l1.y);
            *(uint4*)(base + OFF_X + db + 8704 + xdoff + 16) = make_uint4(l2.x, l2.y, l3.x, l3.y);
            __syncthreads();
        }
    }

    // ---- softmax over m (rows g, 8+g, 16+g if g<4; padded m masked) ----
#pragma unroll
    for (int nf = 0; nf < 2; nf++) {
        float r0[2], r1[2], r2[2];
#pragma unroll
        for (int p = 0; p < 2; p++) {
            const float va = d1[0][nf][p];
            const float vb = d1[0][nf][2 + p];
            const float vc = (g < 4) ? d1[1][nf][p] : -3.0e38f;
            float mx = fmaxf(fmaxf(va, vb), vc);
#pragma unroll
            for (int off = 4; off <= 16; off <<= 1)
                mx = fmaxf(mx, __shfl_xor_sync(0xffffffffu, mx, off));
            const float ea = __expf(va - mx);
            const float eb = __expf(vb - mx);
            const float ec = (g < 4) ? __expf(vc - mx) : 0.0f;
            float s = ea + eb + ec;
#pragma unroll
            for (int off = 4; off <= 16; off <<= 1)
                s += __shfl_xor_sync(0xffffffffu, s, off);
            const float inv = 1.0f / s;
            r0[p] = ea * inv; r1[p] = eb * inv; r2[p] = ec * inv;
        }
        const int coff = (wid * 16 + nf * 8 + (lane & 3) * 2) * 2;
        __nv_bfloat16 h0, l0, h1, l1;
#pragma unroll
        for (int rsel = 0; rsel < 3; rsel++) {
            if (rsel == 2 && g >= 4) break;
            const float* rv = (rsel == 0) ? r0 : (rsel == 1) ? r1 : r2;
            const int row = (rsel == 0) ? g : (rsel == 1) ? 8 + g : 16 + g;
            split1(rv[0], h0, l0); split1(rv[1], h1, l1);
            *(uint32_t*)(base + OFF_ATHI + row * ATS + coff) =
                (uint32_t)__bfloat16_as_ushort(h0) | ((uint32_t)__bfloat16_as_ushort(h1) << 16);
            *(uint32_t*)(base + OFF_ATLO + row * ATS + coff) =
                (uint32_t)__bfloat16_as_ushort(l0) | ((uint32_t)__bfloat16_as_ushort(l1) << 16);
        }
    }
    __syncthreads();

    // ---- GEMM2: new_feat[c][n] = QT[c][m] @ attn[m][n], two n-halves ----
    float* ob = out + ((ll)b * 2 * CODE) * HW + n0;
#pragma unroll
    for (int nh = 0; nh < 2; nh++) {
        float d2[2][8][4];
#pragma unroll
        for (int mf = 0; mf < 2; mf++)
#pragma unroll
            for (int nf = 0; nf < 8; nf++)
#pragma unroll
                for (int k = 0; k < 4; k++) d2[mf][nf][k] = 0.0f;

#pragma unroll
        for (int s = 0; s < 2; s++) {
            uint32_t abh[8][2], abl[8][2];
            const uint32_t br = sb + OFF_ATHI + (s * 16 + (lane & 15)) * ATS + nh * 128;
#pragma unroll
            for (int nf = 0; nf < 8; nf++) {
                ldsm_x2t(abh[nf], br + nf * 16);
                ldsm_x2t(abl[nf], br + nf * 16 + (OFF_ATLO - OFF_ATHI));
            }
#pragma unroll
            for (int mf = 0; mf < 2; mf++) {
                const uint32_t qa = sb + OFF_QTHI + (wid * 32 + mf * 16 + (lane & 15)) * QTS
                                  + (s * 16 + ((lane >> 4) << 3)) * 2;
                uint32_t qh[4], ql[4];
                ldsm_x4(qh, qa);
                ldsm_x4(ql, qa + (OFF_QTLO - OFF_QTHI));
#pragma unroll
                for (int nf = 0; nf < 8; nf++) mma_bf16(d2[mf][nf], qh, abh[nf]);
#pragma unroll
                for (int nf = 0; nf < 8; nf++) mma_bf16(d2[mf][nf], qh, abl[nf]);
#pragma unroll
                for (int nf = 0; nf < 8; nf++) mma_bf16(d2[mf][nf], ql, abh[nf]);
            }
        }
#pragma unroll
        for (int mf = 0; mf < 2; mf++) {
            const int c0 = wid * 32 + mf * 16 + g;
            const int nc = nh * 64 + (lane & 3) * 2;
#pragma unroll
            for (int nf = 0; nf < 8; nf++) {
                *(float2*)(ob + (ll)c0 * HW + nc + nf * 8)       = make_float2(d2[mf][nf][0], d2[mf][nf][1]);
                *(float2*)(ob + (ll)(c0 + 8) * HW + nc + nf * 8) = make_float2(d2[mf][nf][2], d2[mf][nf][3]);
            }
        }
    }
}

// ---------------------------------------------------------------------------
extern "C" void kernel_launch(void* const* d_in, const int* in_sizes, int n_in,
                              void* d_out, int out_size) {
    const float* feats  = (const float*)d_in[0];
    const float* preds  = (const float*)d_in[1];
    const int*   labels = (const int*)  d_in[2];
    const int*   flag   = (const int*)  d_in[3];
    const float* queue  = (const float*)d_in[4];
    const float* Wp     = (const float*)d_in[5];
    const float* bp     = (const float*)d_in[6];
    float* out = (float*)d_out;

    cudaFuncSetAttribute(gemm_proj_mma,
                         cudaFuncAttributeMaxDynamicSharedMemorySize, SMEM_GEMM);
    cudaFuncSetAttribute(queue_scan_kernel,
                         cudaFuncAttributeMaxDynamicSharedMemorySize, SMEM_SCAN);
    cudaFuncSetAttribute(attn_mma_kernel,
                         cudaFuncAttributeMaxDynamicSharedMemorySize, SMEM_ATTN);

    convert_wp<<<CODE * IN_C / 1024, 256>>>(Wp);

    dim3 g1(HW / 128, BB);
    gemm_proj_mma<<<g1, 512, SMEM_GEMM>>>(feats, preds, bp, out);

    feat_reduce_kernel<<<BB, 1024>>>();
    queue_scan_kernel<<<NCLASSES, 672, SMEM_SCAN>>>(queue, labels, flag);
    prep_attn_q<<<NCLASSES, 256>>>();

    dim3 g3(HW / 128, BB);
    attn_mma_kernel<<<g3, 256, SMEM_ATTN>>>(labels, out);
}

// round 12
// speedup vs baseline: 1.6580x; 1.0911x over previous
#include <cuda_runtime.h>
#include <cuda_bf16.h>
#include <cstdint>

#define BB 32
#define IN_C 512
#define HW 4096
#define CODE 256
#define NCLASSES 4
#define MEMN 20
#define DECAYF 0.9f
#define EPSF 1e-12f
#define NTP 128

typedef long long ll;

// Deterministic scratch (no atomics anywhere).
__device__ float g_partial[BB * CODE * NTP];
__device__ float g_feat[BB * CODE];
__device__ float g_queue[NCLASSES * MEMN * CODE];

// Pre-converted bf16 hi/lo of Wp.
__device__ __nv_bfloat16 g_wp_hi[CODE * IN_C];
__device__ __nv_bfloat16 g_wp_lo[CODE * IN_C];

// ---------------------------------------------------------------------------
// helpers
// ---------------------------------------------------------------------------
__device__ __forceinline__ uint32_t smem_u32(const void* p) {
    uint32_t a;
    asm("{ .reg .u64 t; cvta.to.shared.u64 t, %1; cvt.u32.u64 %0, t; }" : "=r"(a) : "l"(p));
    return a;
}
__device__ __forceinline__ void ldsm_x4(uint32_t a[4], uint32_t addr) {
    asm volatile("ldmatrix.sync.aligned.m8n8.x4.shared.b16 {%0,%1,%2,%3}, [%4];"
                 : "=r"(a[0]), "=r"(a[1]), "=r"(a[2]), "=r"(a[3]) : "r"(addr));
}
__device__ __forceinline__ void ldsm_x2t(uint32_t b[2], uint32_t addr) {
    asm volatile("ldmatrix.sync.aligned.m8n8.x2.trans.shared.b16 {%0,%1}, [%2];"
                 : "=r"(b[0]), "=r"(b[1]) : "r"(addr));
}
__device__ __forceinline__ void mma_bf16(float d[4], const uint32_t a[4], const uint32_t b[2]) {
    asm volatile("mma.sync.aligned.m16n8k16.row.col.f32.bf16.bf16.f32 "
                 "{%0,%1,%2,%3}, {%4,%5,%6,%7}, {%8,%9}, {%0,%1,%2,%3};"
                 : "+f"(d[0]), "+f"(d[1]), "+f"(d[2]), "+f"(d[3])
                 : "r"(a[0]), "r"(a[1]), "r"(a[2]), "r"(a[3]), "r"(b[0]), "r"(b[1]));
}
__device__ __forceinline__ void cpasync16(uint32_t dst, const void* src) {
    asm volatile("cp.async.cg.shared.global [%0], [%1], 16;" :: "r"(dst), "l"(src));
}
#define CP_COMMIT() asm volatile("cp.async.commit_group;" ::: "memory")
#define CP_WAIT0()  asm volatile("cp.async.wait_group 0;" ::: "memory")

__device__ __forceinline__ void split4(float4 v, uint2& hi, uint2& lo) {
    __nv_bfloat16 h0 = __float2bfloat16_rn(v.x), h1 = __float2bfloat16_rn(v.y);
    __nv_bfloat16 h2 = __float2bfloat16_rn(v.z), h3 = __float2bfloat16_rn(v.w);
    float r0 = v.x - __bfloat162float(h0), r1 = v.y - __bfloat162float(h1);
    float r2 = v.z - __bfloat162float(h2), r3 = v.w - __bfloat162float(h3);
    __nv_bfloat16 l0 = __float2bfloat16_rn(r0), l1 = __float2bfloat16_rn(r1);
    __nv_bfloat16 l2 = __float2bfloat16_rn(r2), l3 = __float2bfloat16_rn(r3);
    hi.x = (uint32_t)__bfloat16_as_ushort(h0) | ((uint32_t)__bfloat16_as_ushort(h1) << 16);
    hi.y = (uint32_t)__bfloat16_as_ushort(h2) | ((uint32_t)__bfloat16_as_ushort(h3) << 16);
    lo.x = (uint32_t)__bfloat16_as_ushort(l0) | ((uint32_t)__bfloat16_as_ushort(l1) << 16);
    lo.y = (uint32_t)__bfloat16_as_ushort(l2) | ((uint32_t)__bfloat16_as_ushort(l3) << 16);
}

__device__ __forceinline__ int get_label(const int* lab, int i) {
    bool odd_zero = true;
#pragma unroll
    for (int k = 1; k < 32; k += 2) odd_zero &= (lab[k] == 0);
    return odd_zero ? lab[2 * i] : lab[i];
}

// ===========================================================================
// Kernel 0: Wp fp32 -> bf16 hi/lo.
// ===========================================================================
__global__ __launch_bounds__(256) void convert_wp(const float* __restrict__ Wp) {
    const int i = (blockIdx.x * 256 + threadIdx.x) * 4;
    float4 v = *(const float4*)(Wp + i);
    uint2 hi, lo; split4(v, hi, lo);
    *(uint2*)(g_wp_hi + i) = hi;
    *(uint2*)(g_wp_lo + i) = lo;
}

// ===========================================================================
// Kernel 1: HMMA bf16-split GEMM, fused B conversion, M=256 CTA tile.
// (unchanged — feats read once, 512 threads, 16 warps, warp tile 64x32)
// ===========================================================================
#define KC 32
#define NCHUNK 16
#define A_STR 80
#define B_STR 272
#define A_HI 0
#define A_LO 20480
#define B_HI 40960
#define B_LO 49664
#define BUF 58368
#define PREDS (2 * BUF)
#define SMEM_GEMM (PREDS + 512 + 16)

__global__ __launch_bounds__(512, 1) void gemm_proj_mma(
    const float* __restrict__ feats, const float* __restrict__ preds,
    const float* __restrict__ bias_p, float* __restrict__ out)
{
    extern __shared__ char base[];
    const uint32_t sb = smem_u32(base);

    const int t = threadIdx.x, wid = t >> 5, lane = t & 31;
    const int nt = blockIdx.x, b = blockIdx.y;
    const int n0 = nt * 128;
    const int wm = wid & 3;
    const int wn = wid >> 2;

    const int ar = t >> 1, as0 = (t & 1) * 2;
    const __nv_bfloat16* wha = g_wp_hi + (ll)ar * IN_C + as0 * 8;
    const __nv_bfloat16* wla = g_wp_lo + (ll)ar * IN_C + as0 * 8;
    const uint32_t adst = sb + A_HI + ar * A_STR + as0 * 16;

    const int kr = t >> 4, nb = (t & 15) * 8;
    const float* fsrc = feats + ((ll)b * IN_C + kr) * HW + n0 + nb;
    const uint32_t bdst = sb + B_HI + kr * B_STR + nb * 2;

    if (t < 128) ((float*)(base + PREDS))[t] = preds[(ll)b * HW + n0 + t];

    float d[4][4][4];
#pragma unroll
    for (int i = 0; i < 4; i++)
#pragma unroll
        for (int j = 0; j < 4; j++)
#pragma unroll
            for (int k = 0; k < 4; k++) d[i][j][k] = 0.0f;

    float4 bR0, bR1;

    bR0 = *(const float4*)(fsrc);
    bR1 = *(const float4*)(fsrc + 4);
    cpasync16(adst,                      wha);
    cpasync16(adst + 16,                 wha + 8);
    cpasync16(adst + (A_LO - A_HI),      wla);
    cpasync16(adst + (A_LO - A_HI) + 16, wla + 8);
    CP_COMMIT();
    {
        uint2 h0, l0, h1, l1;
        split4(bR0, h0, l0); split4(bR1, h1, l1);
        *(uint4*)(base + (bdst - sb))                 = make_uint4(h0.x, h0.y, h1.x, h1.y);
        *(uint4*)(base + (bdst - sb) + (B_LO - B_HI)) = make_uint4(l0.x, l0.y, l1.x, l1.y);
    }
    CP_WAIT0();
    __syncthreads();

    for (int c = 0; c < NCHUNK; c++) {
        if (c + 1 < NCHUNK) {
            const ll ko = (ll)(c + 1) * KC;
            bR0 = *(const float4*)(fsrc + ko * HW);
            bR1 = *(const float4*)(fsrc + ko * HW + 4);
            const uint32_t db = ((c + 1) & 1) * BUF;
            cpasync16(adst + db,                      wha + ko);
            cpasync16(adst + db + 16,                 wha + ko + 8);
            cpasync16(adst + db + (A_LO - A_HI),      wla + ko);
            cpasync16(adst + db + (A_LO - A_HI) + 16, wla + ko + 8);
            CP_COMMIT();
        }

        const uint32_t bu = sb + (c & 1) * BUF;
#pragma unroll
        for (int s = 0; s < 2; s++) {
            uint32_t bh[4][2], bl[4][2];
            const int krr = s * 16 + (lane & 15);
#pragma unroll
            for (int nf = 0; nf < 4; nf++) {
                uint32_t ba = bu + B_HI + krr * B_STR + (wn * 32 + nf * 8) * 2;
                ldsm_x2t(bh[nf], ba);
                ldsm_x2t(bl[nf], ba + (B_LO - B_HI));
            }
#pragma unroll
            for (int mf = 0; mf < 4; mf++) {
                const int arr = wm * 64 + mf * 16 + (lane & 15);
                const uint32_t acol = (s * 16 + ((lane >> 4) << 3)) * 2;
                uint32_t aa = bu + A_HI + arr * A_STR + acol;
                uint32_t ah[4], al[4];
                ldsm_x4(ah, aa);
                ldsm_x4(al, aa + (A_LO - A_HI));
#pragma unroll
                for (int nf = 0; nf < 4; nf++) mma_bf16(d[mf][nf], ah, bh[nf]);
#pragma unroll
                for (int nf = 0; nf < 4; nf++) mma_bf16(d[mf][nf], ah, bl[nf]);
#pragma unroll
                for (int nf = 0; nf < 4; nf++) mma_bf16(d[mf][nf], al, bh[nf]);
            }
        }
        __syncthreads();

        if (c + 1 < NCHUNK) {
            const uint32_t db = ((c + 1) & 1) * BUF;
            uint2 h0, l0, h1, l1;
            split4(bR0, h0, l0); split4(bR1, h1, l1);
            *(uint4*)(base + (bdst - sb) + db)                 = make_uint4(h0.x, h0.y, h1.x, h1.y);
            *(uint4*)(base + (bdst - sb) + db + (B_LO - B_HI)) = make_uint4(l0.x, l0.y, l1.x, l1.y);
            CP_WAIT0();
        }
        __syncthreads();
    }

    const float* ps = (const float*)(base + PREDS);
    const int r = lane >> 2, cq = lane & 3;
#pragma unroll
    for (int mf = 0; mf < 4; mf++) {
        const int oa = wm * 64 + mf * 16 + r;
        const int oc = oa + 8;
        const float biasa = bias_p[oa], biasb = bias_p[oc];
        float* xa = out + ((ll)b * 2 * CODE + CODE + oa) * HW + n0;
        float* xc = out + ((ll)b * 2 * CODE + CODE + oc) * HW + n0;
        float ra = 0.0f, rb = 0.0f;
#pragma unroll
        for (int nf = 0; nf < 4; nf++) {
            const int nl = wn * 32 + nf * 8 + cq * 2;
            const float p0 = ps[nl], p1 = ps[nl + 1];
            float v0 = d[mf][nf][0] + biasa, v1 = d[mf][nf][1] + biasa;
            float v2 = d[mf][nf][2] + biasb, v3 = d[mf][nf][3] + biasb;
            ra += v0 * p0 + v1 * p1;
            rb += v2 * p0 + v3 * p1;
            *(float2*)(xa + nl) = make_float2(v0, v1);
            *(float2*)(xc + nl) = make_float2(v2, v3);
        }
        ra += __shfl_xor_sync(0xffffffffu, ra, 1);
        ra += __shfl_xor_sync(0xffffffffu, ra, 2);
        rb += __shfl_xor_sync(0xffffffffu, rb, 1);
        rb += __shfl_xor_sync(0xffffffffu, rb, 2);
        if (cq == 0) {
            g_partial[((ll)b * CODE + oa) * NTP + nt * 4 + wn] = ra;
            g_partial[((ll)b * CODE + oc) * NTP + nt * 4 + wn] = rb;
        }
    }
}

// ===========================================================================
// Kernel 2a: parallel feat reduction, coalesced.
// ===========================================================================
__global__ __launch_bounds__(1024) void feat_reduce_kernel() {
    const int gid = blockIdx.x * 1024 + threadIdx.x;
    const int row = gid >> 2, i = gid & 3;
    const float* p = g_partial + (ll)row * NTP + i * 4;
    float s = 0.0f;
#pragma unroll
    for (int q = 0; q < 8; q++) {
        float4 v = *(const float4*)(p + q * 16);
        s += v.x + v.y + v.z + v.w;
    }
    s += __shfl_xor_sync(0xffffffffu, s, 1);
    s += __shfl_xor_sync(0xffffffffu, s, 2);
    if (i == 0) g_feat[row] = s * (1.0f / HW);
}

// ===========================================================================
// Kernel 2b: class-parallel EMA scan (4 blocks, one per class).
// ===========================================================================
#define SMEM_SCAN ((MEMN * CODE + BB * CODE + 96) * 4)

__global__ __launch_bounds__(672) void queue_scan_kernel(
    const float* __restrict__ queue_in, const int* __restrict__ labels_raw,
    const int* __restrict__ flag)
{
    extern __shared__ float sm[];
    float* s_q = sm;
    float* s_feat = sm + MEMN * CODE;
    float* s_logit = s_feat + BB * CODE;
    float* s_fnorm = s_logit + MEMN;
    float* s_coef  = s_fnorm + 1;
    int*   s_lab   = (int*)(s_coef + MEMN);

    const int cls = blockIdx.x;
    const int t = threadIdx.x;
    const float* qsrc = queue_in + (ll)cls * MEMN * CODE;
    for (int i = t; i < MEMN * CODE; i += 672) s_q[i] = qsrc[i];
    for (int i = t; i < BB * CODE; i += 672) s_feat[i] = g_feat[i];
    if (t < BB) s_lab[t] = get_label(labels_raw, t);
    __syncthreads();

    if (*flag == 1) {
        const int warp = t >> 5, lane = t & 31;
        for (int b = 0; b < BB; b++) {
            if (s_lab[b] != cls) continue;
            const float* f = s_feat + b * CODE;

            if (warp < MEMN) {
                const float* slot = s_q + warp * CODE;
                float s = 0.0f;
#pragma unroll
                for (int c = lane; c < CODE; c += 32) s += slot[c] * f[c];
#pragma unroll
                for (int off = 16; off; off >>= 1) s += __shfl_xor_sync(0xffffffffu, s, off);
                if (lane == 0) s_logit[warp] = s;
            } else {
                float s = 0.0f;
#pragma unroll
                for (int c = lane; c < CODE; c += 32) { float v = f[c]; s += v * v; }
#pragma unroll
                for (int off = 16; off; off >>= 1) s += __shfl_xor_sync(0xffffffffu, s, off);
                if (lane == 0) *s_fnorm = sqrtf(s);
            }
            __syncthreads();

            if (t < MEMN) {
                const float lg = s_logit[t];
                const float denom = fmaxf(fabsf(lg) * (*s_fnorm), EPSF);
                s_coef[t] = (1.0f - DECAYF) * lg / denom;
            }
            __syncthreads();

            for (int i = t; i < MEMN * CODE; i += 672) {
                const int m = i >> 8, c = i & 255;
                s_q[i] = DECAYF * s_q[i] + s_coef[m] * f[c];
            }
            __syncthreads();
        }
    }

    float* qdst = g_queue + (ll)cls * MEMN * CODE;
    for (int i = t; i < MEMN * CODE; i += 672) qdst[i] = s_q[i];
}

// ===========================================================================
// Kernel 3: SIMT memory attention (round-9 measured winner).
// Grid (HW/256, B) = 512 blocks, 128 threads, 2 n/thread.
// ===========================================================================
__global__ __launch_bounds__(128) void attn_kernel(
    const int* __restrict__ labels_raw, float* __restrict__ out)
{
    const int b = blockIdx.y, n0 = blockIdx.x * 256, t = threadIdx.x;

    __shared__ float sq[MEMN][CODE];
    const int l = get_label(labels_raw, b);
    const float* qsrc = g_queue + (ll)l * MEMN * CODE;
    for (int i = t * 4; i < MEMN * CODE; i += 512)
        *(float4*)(&sq[0][0] + i) = *(const float4*)(qsrc + i);
    __syncthreads();

    const float* xb = out + ((ll)b * 2 * CODE + CODE) * HW;
    float* ob = out + ((ll)b * 2 * CODE) * HW;
    const int j = n0 + t * 2;

    float a0[MEMN], a1[MEMN];
#pragma unroll
    for (int m = 0; m < MEMN; m++) { a0[m] = 0.f; a1[m] = 0.f; }

#pragma unroll 1
    for (int cqd = 0; cqd < 64; cqd++) {
        const float* xp = xb + (ll)cqd * 4 * HW + j;
        float2 x0 = *(const float2*)(xp);
        float2 x1 = *(const float2*)(xp + HW);
        float2 x2 = *(const float2*)(xp + 2 * HW);
        float2 x3 = *(const float2*)(xp + 3 * HW);
#pragma unroll
        for (int m = 0; m < MEMN; m++) {
            float4 qv = *(const float4*)&sq[m][cqd * 4];
            a0[m] += qv.x * x0.x + qv.y * x1.x + qv.z * x2.x + qv.w * x3.x;
            a1[m] += qv.x * x0.y + qv.y * x1.y + qv.z * x2.y + qv.w * x3.y;
        }
    }

    float m0 = a0[0], m1 = a1[0];
#pragma unroll
    for (int m = 1; m < MEMN; m++) { m0 = fmaxf(m0, a0[m]); m1 = fmaxf(m1, a1[m]); }
    float s0 = 0.f, s1 = 0.f;
#pragma unroll
    for (int m = 0; m < MEMN; m++) {
        a0[m] = __expf(a0[m] - m0); s0 += a0[m];
        a1[m] = __expf(a1[m] - m1); s1 += a1[m];
    }
    const float i0 = 1.f / s0, i1 = 1.f / s1;
#pragma unroll
    for (int m = 0; m < MEMN; m++) { a0[m] *= i0; a1[m] *= i1; }

#pragma unroll 1
    for (int cqd = 0; cqd < 64; cqd++) {
        float o0x = 0.f, o0y = 0.f, o1x = 0.f, o1y = 0.f;
        float o2x = 0.f, o2y = 0.f, o3x = 0.f, o3y = 0.f;
#pragma unroll
        for (int m = 0; m < MEMN; m++) {
            float4 qv = *(const float4*)&sq[m][cqd * 4];
            o0x += qv.x * a0[m]; o0y += qv.x * a1[m];
            o1x += qv.y * a0[m]; o1y += qv.y * a1[m];
            o2x += qv.z * a0[m]; o2y += qv.z * a1[m];
            o3x += qv.w * a0[m]; o3y += qv.w * a1[m];
        }
        float* op = ob + (ll)cqd * 4 * HW + j;
        *(float2*)(op)          = make_float2(o0x, o0y);
        *(float2*)(op + HW)     = make_float2(o1x, o1y);
        *(float2*)(op + 2 * HW) = make_float2(o2x, o2y);
        *(float2*)(op + 3 * HW) = make_float2(o3x, o3y);
    }
}

// ---------------------------------------------------------------------------
extern "C" void kernel_launch(void* const* d_in, const int* in_sizes, int n_in,
                              void* d_out, int out_size) {
    const float* feats  = (const float*)d_in[0];
    const float* preds  = (const float*)d_in[1];
    const int*   labels = (const int*)  d_in[2];
    const int*   flag   = (const int*)  d_in[3];
    const float* queue  = (const float*)d_in[4];
    const float* Wp     = (const float*)d_in[5];
    const float* bp     = (const float*)d_in[6];
    float* out = (float*)d_out;

    cudaFuncSetAttribute(gemm_proj_mma,
                         cudaFuncAttributeMaxDynamicSharedMemorySize, SMEM_GEMM);
    cudaFuncSetAttribute(queue_scan_kernel,
                         cudaFuncAttributeMaxDynamicSharedMemorySize, SMEM_SCAN);

    convert_wp<<<CODE * IN_C / 1024, 256>>>(Wp);

    dim3 g1(HW / 128, BB);
    gemm_proj_mma<<<g1, 512, SMEM_GEMM>>>(feats, preds, bp, out);

    feat_reduce_kernel<<<BB, 1024>>>();
    queue_scan_kernel<<<NCLASSES, 672, SMEM_SCAN>>>(queue, labels, flag);

    dim3 g3(HW / 256, BB);
    attn_kernel<<<g3, 128>>>(labels, out);
}